// round 9
// baseline (speedup 1.0000x reference)
#include <cuda_runtime.h>
#include <cuda_bf16.h>
#include <math.h>
#include <stdint.h>

#define HW 65536
#define BATCH 4
#define NSEG 32
#define GCH 128
#define GPAD 140

// ---------------- static scratch ----------------
__device__ float g_qkv [(size_t)BATCH * 288 * HW];   // qkv pre-dwconv; later gated FFN 'g'
__device__ float g_qkvd[(size_t)BATCH * 288 * HW];   // qkv post-dwconv (q|k|v)
__device__ float g_svpq[(size_t)BATCH * 12  * HW];   // svp_q
__device__ float g_mu  [(size_t)BATCH * HW];
__device__ float g_rs  [(size_t)BATCH * HW];
__device__ float g_ss  [BATCH * 204];
__device__ float g_gp  [NSEG * 16 * 648];
__device__ __nv_bfloat16 g_Mh [BATCH * 96 * 96];
__device__ __nv_bfloat16 g_Ml [BATCH * 96 * 96];
__device__ __nv_bfloat16 g_Aqh[288 * 96];
__device__ __nv_bfloat16 g_Aql[288 * 96];
__device__ float g_bq  [288];
__device__ __nv_bfloat16 g_Agh[512 * 96];
__device__ __nv_bfloat16 g_Agl[512 * 96];
__device__ float g_bg  [512];
__device__ __nv_bfloat16 g_Fh [96 * 256];
__device__ __nv_bfloat16 g_Fl [96 * 256];

// ---------------- helpers ----------------
__device__ __forceinline__ void bsplit(float v, __nv_bfloat16& h, __nv_bfloat16& l) {
    h = __float2bfloat16(v);
    l = __float2bfloat16(v - __bfloat162float(h));
}
__device__ __forceinline__ void split2(float a, float b, uint32_t& h, uint32_t& l) {
    __nv_bfloat16 ha = __float2bfloat16(a), hb = __float2bfloat16(b);
    __nv_bfloat16 la = __float2bfloat16(a - __bfloat162float(ha));
    __nv_bfloat16 lb = __float2bfloat16(b - __bfloat162float(hb));
    __nv_bfloat162 hv(ha, hb), lv(la, lb);
    h = *(uint32_t*)&hv; l = *(uint32_t*)&lv;
}
__device__ __forceinline__ uint32_t s2u(const void* p) {
    return (uint32_t)__cvta_generic_to_shared(p);
}
__device__ __forceinline__ void ldsm4(uint32_t* r, uint32_t addr) {
    asm volatile("ldmatrix.sync.aligned.m8n8.x4.shared.b16 {%0,%1,%2,%3}, [%4];"
        : "=r"(r[0]), "=r"(r[1]), "=r"(r[2]), "=r"(r[3]) : "r"(addr));
}
__device__ __forceinline__ void ldsm4t(uint32_t* r, uint32_t addr) {
    asm volatile("ldmatrix.sync.aligned.m8n8.x4.trans.shared.b16 {%0,%1,%2,%3}, [%4];"
        : "=r"(r[0]), "=r"(r[1]), "=r"(r[2]), "=r"(r[3]) : "r"(addr));
}
__device__ __forceinline__ void mma_bf16(float* d, const uint32_t* a, const uint32_t* b) {
    asm volatile("mma.sync.aligned.m16n8k16.row.col.f32.bf16.bf16.f32 "
        "{%0,%1,%2,%3}, {%4,%5,%6,%7}, {%8,%9}, {%0,%1,%2,%3};"
        : "+f"(d[0]), "+f"(d[1]), "+f"(d[2]), "+f"(d[3])
        : "r"(a[0]), "r"(a[1]), "r"(a[2]), "r"(a[3]), "r"(b[0]), "r"(b[1]));
}
__device__ __forceinline__ void cp16(uint32_t saddr, const void* g, int sz) {
    asm volatile("cp.async.ca.shared.global [%0], [%1], 16, %2;"
        :: "r"(saddr), "l"(g), "r"(sz));
}
__device__ __forceinline__ void cp_commit() { asm volatile("cp.async.commit_group;"); }
__device__ __forceinline__ void cp_wait0()  { asm volatile("cp.async.wait_group 0;" ::: "memory"); }
__device__ __forceinline__ float gatef(float a, float bb) {
    float sig = 1.f / (1.f + expf(-bb));
    float gel = 0.5f * a * (1.f + erff(a * 0.70710678118654752f));
    return a * sig + bb * gel;
}

// ---------------- prep: fold LN weights, split to bf16 hi/lo ----------------
__global__ void prep_kernel(const float* __restrict__ qkv_w,
                            const float* __restrict__ n1w, const float* __restrict__ n1b,
                            const float* __restrict__ ffn1_w, const float* __restrict__ ffn2_w,
                            const float* __restrict__ n2w, const float* __restrict__ n2b,
                            const float* __restrict__ ffn_out_w) {
    int r = blockIdx.x;
    int k = threadIdx.x;  // 0..95
    __shared__ float red[96];
    if (r < 288) {
        float wv = qkv_w[r * 96 + k];
        bsplit(wv * n1w[k], g_Aqh[r * 96 + k], g_Aql[r * 96 + k]);
        red[k] = wv * n1b[k];
        __syncthreads();
        if (k == 0) { float s = 0.f; for (int j = 0; j < 96; j++) s += red[j]; g_bq[r] = s; }
    } else if (r < 800) {
        int c = r - 288;                  // 0..511
        int T = c >> 4, wi = c & 15;
        int g = T * 8 + (wi & 7);
        bool valid = (g < 255);
        const float* W = (wi < 8) ? ffn1_w : ffn2_w;
        float wv = valid ? W[g * 96 + k] : 0.f;
        bsplit(wv * n2w[k], g_Agh[c * 96 + k], g_Agl[c * 96 + k]);
        red[k] = wv * n2b[k];
        __syncthreads();
        if (k == 0) {
            float s = 0.f; for (int j = 0; j < 96; j++) s += red[j];
            if (valid) g_bg[(wi < 8 ? 0 : 256) + g] = s;
        }
    } else {
        int o = r - 800;                  // 0..95
        for (int kk = k; kk < 256; kk += 96) {
            float v = (kk < 255) ? ffn_out_w[o * 255 + kk] : 0.f;
            bsplit(v, g_Fh[o * 256 + kk], g_Fl[o * 256 + kk]);
        }
    }
}

// ---------------- LN stats (LN1 only; LN2 fused into gemm8 epilogue) ----------------
__global__ void ln_stats(const float* __restrict__ x, float* __restrict__ mu,
                         float* __restrict__ rs) {
    int i = blockIdx.x * blockDim.x + threadIdx.x;
    if (i >= BATCH * HW) return;
    int b = i >> 16, pix = i & 65535;
    const float* xp = x + (long long)b * 96 * HW + pix;
    float sum = 0.f, sq = 0.f;
    #pragma unroll 8
    for (int c = 0; c < 96; c++) {
        float v = xp[(long long)c * HW];
        sum += v; sq += v * v;
    }
    float m = sum * (1.f / 96.f);
    float var = sq * (1.f / 96.f) - m * m;
    mu[i] = m;
    rs[i] = rsqrtf(var + 1e-5f);
}

// ---------------- tensor-core GEMM: C[M,N=65536] = A[M,K]@B[K,N], split-bf16 ----------------
// BM=BN=128, BK=32, 256 threads (4x2 warps of 32x64). A via cp.async (row-major smem),
// B via vectorized split-stash. EPI: 0 plain(+RESID), 1 +bias, 2 dual-gate.
// STATS: fused per-pixel LN stats on output (requires gridDim.y==1, M<=96*? uses wm<3).
template <int EPI, int LN, int RESID, int STATS>
__global__ __launch_bounds__(256) void gemm_t(
    const __nv_bfloat16* __restrict__ Ah, const __nv_bfloat16* __restrict__ Al,
    const float* __restrict__ B, const float* __restrict__ R, float* __restrict__ C,
    const float* __restrict__ bias,
    const float* __restrict__ mu, const float* __restrict__ rs,
    float* __restrict__ muo, float* __restrict__ rso,
    int M, int K, int Kpad,
    long long sA, long long sB, long long sR, long long sC)
{
    extern __shared__ __align__(16) char smem_raw[];
    __nv_bfloat16* Ash = (__nv_bfloat16*)smem_raw;   // [2][128][40]
    __nv_bfloat16* Asl = Ash + 10240;                // [2][128][40]
    __nv_bfloat16* Bsh = Asl + 10240;                // [2][32][136]
    __nv_bfloat16* Bsl = Bsh + 8704;                 // [2][32][136]

    Ah += (long long)blockIdx.z * sA;
    Al += (long long)blockIdx.z * sA;
    B  += (long long)blockIdx.z * sB;
    C  += (long long)blockIdx.z * sC;
    if (RESID) R += (long long)blockIdx.z * sR;
    if (LN) { mu += (long long)blockIdx.z * HW; rs += (long long)blockIdx.z * HW; }

    const int m_base = blockIdx.y * 128;
    const int n_base = blockIdx.x * 128;
    const int tid  = threadIdx.x;
    const int lane = tid & 31;
    const int warp = tid >> 5;
    const int wm = warp >> 1, wn = warp & 1;

    // A cp.async coords
    const int a_row = tid & 127;
    const int a_kc  = tid >> 7;         // kc = a_kc + 2j
    // B loader coords: 8 consecutive n, 2 k rows
    const int b_k  = tid >> 4;          // + 16j
    const int b_ng = tid & 15;

    float4 m4[2], r4[2];
    if (LN) {
        m4[0] = *(const float4*)(mu + n_base + b_ng * 8);
        m4[1] = *(const float4*)(mu + n_base + b_ng * 8 + 4);
        r4[0] = *(const float4*)(rs + n_base + b_ng * 8);
        r4[1] = *(const float4*)(rs + n_base + b_ng * 8 + 4);
    }

    float acc[2][8][4];
    #pragma unroll
    for (int i = 0; i < 2; i++)
        #pragma unroll
        for (int j = 0; j < 8; j++)
            #pragma unroll
            for (int q = 0; q < 4; q++) acc[i][j][q] = 0.f;

    const int nst = (K + 31) >> 5;
    uint4 rbh[2], rbl[2];

    auto cpA = [&](int kg, int buf) {
        int grow = m_base + a_row;
        int sz = (grow < M) ? 16 : 0;
        long long base = (long long)(grow < M ? grow : 0) * Kpad + kg;
        #pragma unroll
        for (int j = 0; j < 2; j++) {
            int kc = a_kc + 2 * j;
            int soff = buf * 5120 + a_row * 40 + kc * 8;
            cp16(s2u(&Ash[soff]), Ah + base + kc * 8, sz);
            cp16(s2u(&Asl[soff]), Al + base + kc * 8, sz);
        }
    };
    auto fetchB = [&](int kg) {
        #pragma unroll
        for (int j = 0; j < 2; j++) {
            int kb = kg + b_k + 16 * j;
            float4 v0 = make_float4(0.f, 0.f, 0.f, 0.f), v1 = v0;
            if (kb < K) {
                v0 = *(const float4*)(B + (long long)kb * HW + n_base + b_ng * 8);
                v1 = *(const float4*)(B + (long long)kb * HW + n_base + b_ng * 8 + 4);
                if (LN) {
                    v0.x = (v0.x - m4[0].x) * r4[0].x; v0.y = (v0.y - m4[0].y) * r4[0].y;
                    v0.z = (v0.z - m4[0].z) * r4[0].z; v0.w = (v0.w - m4[0].w) * r4[0].w;
                    v1.x = (v1.x - m4[1].x) * r4[1].x; v1.y = (v1.y - m4[1].y) * r4[1].y;
                    v1.z = (v1.z - m4[1].z) * r4[1].z; v1.w = (v1.w - m4[1].w) * r4[1].w;
                }
            }
            split2(v0.x, v0.y, rbh[j].x, rbl[j].x);
            split2(v0.z, v0.w, rbh[j].y, rbl[j].y);
            split2(v1.x, v1.y, rbh[j].z, rbl[j].z);
            split2(v1.z, v1.w, rbh[j].w, rbl[j].w);
        }
    };
    auto stashB = [&](int buf) {
        #pragma unroll
        for (int j = 0; j < 2; j++) {
            int kb = b_k + 16 * j;
            *(uint4*)&Bsh[buf * 4352 + kb * 136 + b_ng * 8] = rbh[j];
            *(uint4*)&Bsl[buf * 4352 + kb * 136 + b_ng * 8] = rbl[j];
        }
    };

    // prologue
    cpA(0, 0);
    cp_commit();
    fetchB(0);
    stashB(0);
    cp_wait0();
    __syncthreads();

    // ldmatrix lane offsets
    const int a_r  = lane & 15;
    const int a_c  = (lane >> 4) << 3;
    const int b_r  = (lane & 7) + ((lane >> 3) & 1) * 8;
    const int b_c  = ((lane >> 4) & 1) * 8 + wn * 64;

    for (int s = 0; s < nst; s++) {
        int buf = s & 1;
        if (s + 1 < nst) {
            cpA((s + 1) * 32, buf ^ 1);
            cp_commit();
            fetchB((s + 1) * 32);
        }
        #pragma unroll
        for (int step = 0; step < 2; step++) {
            uint32_t ah[2][4], al[2][4];
            #pragma unroll
            for (int i = 0; i < 2; i++) {
                int off = buf * 5120 + (wm * 32 + i * 16 + a_r) * 40 + step * 16 + a_c;
                ldsm4(ah[i], s2u(&Ash[off]));
                ldsm4(al[i], s2u(&Asl[off]));
            }
            uint32_t bh[4][4], bl[4][4];
            #pragma unroll
            for (int jp = 0; jp < 4; jp++) {
                int off = buf * 4352 + (step * 16 + b_r) * 136 + b_c + jp * 16;
                ldsm4t(bh[jp], s2u(&Bsh[off]));
                ldsm4t(bl[jp], s2u(&Bsl[off]));
            }
            #pragma unroll
            for (int i = 0; i < 2; i++) {
                #pragma unroll
                for (int j = 0; j < 8; j++) {
                    int jp = j >> 1;
                    const uint32_t* bhp = (j & 1) ? bh[jp] + 2 : bh[jp];
                    const uint32_t* blp = (j & 1) ? bl[jp] + 2 : bl[jp];
                    mma_bf16(acc[i][j], ah[i], bhp);
                    mma_bf16(acc[i][j], ah[i], blp);
                    mma_bf16(acc[i][j], al[i], bhp);
                }
            }
        }
        if (s + 1 < nst) {
            stashB(buf ^ 1);
            cp_wait0();
        }
        __syncthreads();
    }

    // ---------------- epilogue ----------------
    float ls[16], ls2[16];
    if (STATS) {
        #pragma unroll
        for (int e = 0; e < 16; e++) { ls[e] = 0.f; ls2[e] = 0.f; }
    }

    if (EPI == 2) {
        #pragma unroll
        for (int i = 0; i < 2; i++) {
            int T = (m_base >> 4) + wm * 2 + i;
            int g = T * 8 + (lane >> 2);
            if (g < 255) {
                float b1 = bias[g], b2 = bias[256 + g];
                #pragma unroll
                for (int j = 0; j < 8; j++) {
                    int col = n_base + wn * 64 + j * 8 + 2 * (lane & 3);
                    float2 v;
                    v.x = gatef(acc[i][j][0] + b1, acc[i][j][2] + b2);
                    v.y = gatef(acc[i][j][1] + b1, acc[i][j][3] + b2);
                    *(float2*)(C + (long long)g * HW + col) = v;
                }
            }
        }
    } else {
        #pragma unroll
        for (int i = 0; i < 2; i++) {
            int r0 = m_base + wm * 32 + i * 16 + (lane >> 2);
            int r1 = r0 + 8;
            float bv0 = 0.f, bv1 = 0.f;
            if (EPI == 1) {
                if (r0 < M) bv0 = bias[r0];
                if (r1 < M) bv1 = bias[r1];
            }
            #pragma unroll
            for (int j = 0; j < 8; j++) {
                int col = n_base + wn * 64 + j * 8 + 2 * (lane & 3);
                if (r0 < M) {
                    float2 v = make_float2(acc[i][j][0] + bv0, acc[i][j][1] + bv0);
                    long long o = (long long)r0 * HW + col;
                    if (RESID) { float2 rr = *(const float2*)(R + o); v.x += rr.x; v.y += rr.y; }
                    *(float2*)(C + o) = v;
                    if (STATS) {
                        ls[2 * j] += v.x; ls[2 * j + 1] += v.y;
                        ls2[2 * j] += v.x * v.x; ls2[2 * j + 1] += v.y * v.y;
                    }
                }
                if (r1 < M) {
                    float2 v = make_float2(acc[i][j][2] + bv1, acc[i][j][3] + bv1);
                    long long o = (long long)r1 * HW + col;
                    if (RESID) { float2 rr = *(const float2*)(R + o); v.x += rr.x; v.y += rr.y; }
                    *(float2*)(C + o) = v;
                    if (STATS) {
                        ls[2 * j] += v.x; ls[2 * j + 1] += v.y;
                        ls2[2 * j] += v.x * v.x; ls2[2 * j + 1] += v.y * v.y;
                    }
                }
            }
        }
    }

    if (STATS) {
        __syncthreads();
        float* sstat = (float*)smem_raw;   // [0..127]=sum, [128..255]=sumsq
        sstat[tid] = 0.f;
        __syncthreads();
        if (wm < 3) {   // M=96: only warps wm 0..2 hold valid rows
            #pragma unroll
            for (int o = 16; o >= 4; o >>= 1) {
                #pragma unroll
                for (int e = 0; e < 16; e++) {
                    ls[e]  += __shfl_down_sync(0xffffffffu, ls[e],  o);
                    ls2[e] += __shfl_down_sync(0xffffffffu, ls2[e], o);
                }
            }
            if (lane < 4) {
                #pragma unroll
                for (int e = 0; e < 16; e++) {
                    int j = e >> 1, q = e & 1;
                    int nl = wn * 64 + j * 8 + 2 * lane + q;
                    atomicAdd(&sstat[nl], ls[e]);
                    atomicAdd(&sstat[128 + nl], ls2[e]);
                }
            }
        }
        __syncthreads();
        if (tid < 128) {
            float sm = sstat[tid] * (1.f / 96.f);
            float sq = sstat[tid + 128] * (1.f / 96.f);
            float var = sq - sm * sm;
            muo[(long long)blockIdx.z * HW + n_base + tid] = sm;
            rso[(long long)blockIdx.z * HW + n_base + tid] = rsqrtf(var + 1e-5f);
        }
    }
}

// ---------------- 3x3 depthwise conv: 32x32 tile, float4 I/O ----------------
__global__ __launch_bounds__(256) void dwconv3(const float* __restrict__ in,
                                               const float* __restrict__ w,
                                               float* __restrict__ out) {
    int zc = blockIdx.z;
    int c = zc % 288;
    const float* src = in  + (long long)zc * HW;
    float*       dst = out + (long long)zc * HW;
    int ox = blockIdx.x * 32, oy = blockIdx.y * 32;
    __shared__ float s[34][40];    // col c <-> gx = ox-4+c ; needed cols 3..36
    int tid = threadIdx.x;
    #pragma unroll
    for (int j = 0; j < 2; j++) {
        int sl = tid + j * 256;
        if (sl < 340) {
            int r = sl / 10, q = sl - r * 10;
            int gy = oy + r - 1, gx = ox - 4 + q * 4;
            float4 v = make_float4(0.f, 0.f, 0.f, 0.f);
            if (gy >= 0 && gy < 256 && gx >= 0 && gx <= 252)
                v = *(const float4*)(src + gy * 256 + gx);
            *(float4*)&s[r][q * 4] = v;
        }
    }
    __syncthreads();
    const float* wc = w + c * 9;
    float w00 = wc[0], w01 = wc[1], w02 = wc[2];
    float w10 = wc[3], w11 = wc[4], w12 = wc[5];
    float w20 = wc[6], w21 = wc[7], w22 = wc[8];
    int row  = tid >> 3;           // 0..31
    int colq = (tid & 7) * 4;      // 0..28
    float v[3][6];
    #pragma unroll
    for (int dr = 0; dr < 3; dr++) {
        float4 m = *(const float4*)&s[row + dr][colq + 4];
        v[dr][0] = s[row + dr][colq + 3];
        v[dr][1] = m.x; v[dr][2] = m.y; v[dr][3] = m.z; v[dr][4] = m.w;
        v[dr][5] = s[row + dr][colq + 8];
    }
    float4 o;
    float* op = (float*)&o;
    #pragma unroll
    for (int t = 0; t < 4; t++) {
        op[t] = w00 * v[0][t] + w01 * v[0][t + 1] + w02 * v[0][t + 2]
              + w10 * v[1][t] + w11 * v[1][t + 1] + w12 * v[1][t + 2]
              + w20 * v[2][t] + w21 * v[2][t + 1] + w22 * v[2][t + 2];
    }
    *(float4*)(dst + (oy + row) * 256 + ox + colq) = o;
}

// ---------------- svp 1x1 conv ----------------
__global__ void svp_kernel(const float* __restrict__ fea, const float* __restrict__ w,
                           float* __restrict__ out) {
    int i = blockIdx.x * blockDim.x + threadIdx.x;
    if (i >= BATCH * HW) return;
    int b = i >> 16, pix = i & 65535;
    const float* f = fea + (long long)b * 3 * HW + pix;
    float f0 = f[0], f1 = f[HW], f2 = f[2 * HW];
    float* o = out + (long long)b * 12 * HW + pix;
    #pragma unroll
    for (int r = 0; r < 12; r++)
        o[(long long)r * HW] = w[r * 3] * f0 + w[r * 3 + 1] * f1 + w[r * 3 + 2] * f2;
}

// ---------------- per-row sum of squares ----------------
__global__ void sumsq_kernel(const float* __restrict__ qkvd, const float* __restrict__ svpq,
                             float* __restrict__ ss) {
    int bid = blockIdx.x;
    int b = bid / 204, r = bid % 204;
    const float* row = (r < 192) ? qkvd + ((long long)b * 288 + r) * HW
                                 : svpq + ((long long)b * 12 + (r - 192)) * HW;
    float acc = 0.f;
    for (int i = threadIdx.x * 4; i < HW; i += blockDim.x * 4) {
        float4 v = *(const float4*)(row + i);
        acc += v.x * v.x + v.y * v.y + v.z * v.z + v.w * v.w;
    }
    __shared__ float red[256];
    red[threadIdx.x] = acc;
    __syncthreads();
    for (int st = 128; st > 0; st >>= 1) {
        if (threadIdx.x < st) red[threadIdx.x] += red[threadIdx.x + st];
        __syncthreads();
    }
    if (threadIdx.x == 0) ss[bid] = red[0];
}

// ---------------- Gram partials ----------------
__global__ __launch_bounds__(672) void gram_kernel(const float* __restrict__ qkvd,
                                                   const float* __restrict__ svpq,
                                                   float* __restrict__ gp) {
    __shared__ float qs[27 * GPAD];
    __shared__ float ks[24 * GPAD];
    int seg = blockIdx.x;
    int bh  = blockIdx.y;
    int b = bh >> 2, h = bh & 3;
    int tid = threadIdx.x;
    int c = tid / 24, d = tid % 24;
    bool active = tid < 648;
    long long segoff = (long long)seg * (HW / NSEG);
    float acc = 0.f;

    for (int ch = 0; ch < HW / NSEG; ch += GCH) {
        for (int i = tid; i < 51 * (GCH / 4); i += 672) {
            int row = i / (GCH / 4), col4 = i % (GCH / 4);
            const float* src;
            float* dstb;
            if (row < 27) {
                src = (row < 24) ? qkvd + ((long long)b * 288 + h * 24 + row) * HW
                                 : svpq + ((long long)b * 12 + h * 3 + (row - 24)) * HW;
                dstb = qs + row * GPAD;
            } else {
                int rr = row - 27;
                src = qkvd + ((long long)b * 288 + 96 + h * 24 + rr) * HW;
                dstb = ks + rr * GPAD;
            }
            *(float4*)(dstb + col4 * 4) = *(const float4*)(src + segoff + ch + col4 * 4);
        }
        __syncthreads();
        if (active) {
            const float4* q4 = (const float4*)(qs + c * GPAD);
            const float4* k4 = (const float4*)(ks + d * GPAD);
            #pragma unroll 8
            for (int p = 0; p < GCH / 4; p++) {
                float4 qv = q4[p], kv = k4[p];
                acc += qv.x * kv.x + qv.y * kv.y + qv.z * kv.z + qv.w * kv.w;
            }
        }
        __syncthreads();
    }
    if (active) gp[((long long)seg * 16 + bh) * 648 + tid] = acc;
}

// ---------------- attn softmax + fold proj_out -> M[b] (bf16 split) ----------------
__global__ void attnm_kernel(const float* __restrict__ gp, const float* __restrict__ ss,
                             const float* __restrict__ temp, const float* __restrict__ projw,
                             __nv_bfloat16* __restrict__ Mh, __nv_bfloat16* __restrict__ Ml) {
    int b = blockIdx.x;
    __shared__ float attn_s[4][27][24];
    int tid = threadIdx.x;
    if (tid < 108) {
        int h = tid / 27, c = tid % 27;
        float ssq = (c < 24) ? ss[b * 204 + h * 24 + c]
                             : ss[b * 204 + 192 + h * 3 + (c - 24)];
        float nq = fmaxf(sqrtf(ssq), 1e-12f);
        float t = temp[h];
        float row[24];
        #pragma unroll
        for (int d = 0; d < 24; d++) {
            float g = 0.f;
            for (int s = 0; s < NSEG; s++)
                g += gp[((long long)s * 16 + b * 4 + h) * 648 + c * 24 + d];
            float nk = fmaxf(sqrtf(ss[b * 204 + 96 + h * 24 + d]), 1e-12f);
            row[d] = g * t / (nq * nk);
        }
        float mx = row[0];
        #pragma unroll
        for (int d = 1; d < 24; d++) mx = fmaxf(mx, row[d]);
        float sum = 0.f;
        #pragma unroll
        for (int d = 0; d < 24; d++) { row[d] = expf(row[d] - mx); sum += row[d]; }
        float inv = 1.f / sum;
        #pragma unroll
        for (int d = 0; d < 24; d++) attn_s[h][c][d] = row[d] * inv;
    }
    __syncthreads();
    for (int e = tid; e < 96 * 96; e += blockDim.x) {
        int o = e / 96, col = e % 96;
        int h = col / 24, d = col % 24;
        float s = 0.f;
        #pragma unroll
        for (int c = 0; c < 27; c++)
            s += projw[o * 108 + h * 27 + c] * attn_s[h][c][d];
        bsplit(s, Mh[b * 9216 + e], Ml[b * 9216 + e]);
    }
}

// ---------------- launch ----------------
extern "C" void kernel_launch(void* const* d_in, const int* in_sizes, int n_in,
                              void* d_out, int out_size) {
    const float* x           = (const float*)d_in[0];
    const float* svp_fea     = (const float*)d_in[1];
    const float* n1w         = (const float*)d_in[2];
    const float* n1b         = (const float*)d_in[3];
    const float* qkv_w       = (const float*)d_in[4];
    const float* qkv_dw_w    = (const float*)d_in[5];
    const float* svp_w       = (const float*)d_in[6];
    const float* temperature = (const float*)d_in[7];
    const float* proj_out_w  = (const float*)d_in[8];
    const float* n2w         = (const float*)d_in[9];
    const float* n2b         = (const float*)d_in[10];
    const float* ffn1_w      = (const float*)d_in[11];
    const float* ffn2_w      = (const float*)d_in[12];
    const float* ffn_out_w   = (const float*)d_in[13];
    float* out = (float*)d_out;

    float *qkv, *qkvd, *svpq, *mu, *rs, *ss, *gp, *bq, *bg;
    __nv_bfloat16 *Mh, *Ml, *Aqh, *Aql, *Agh, *Agl, *Fh, *Fl;
    cudaGetSymbolAddress((void**)&qkv,  g_qkv);
    cudaGetSymbolAddress((void**)&qkvd, g_qkvd);
    cudaGetSymbolAddress((void**)&svpq, g_svpq);
    cudaGetSymbolAddress((void**)&mu,   g_mu);
    cudaGetSymbolAddress((void**)&rs,   g_rs);
    cudaGetSymbolAddress((void**)&ss,   g_ss);
    cudaGetSymbolAddress((void**)&gp,   g_gp);
    cudaGetSymbolAddress((void**)&Mh,   g_Mh);
    cudaGetSymbolAddress((void**)&Ml,   g_Ml);
    cudaGetSymbolAddress((void**)&Aqh,  g_Aqh);
    cudaGetSymbolAddress((void**)&Aql,  g_Aql);
    cudaGetSymbolAddress((void**)&bq,   g_bq);
    cudaGetSymbolAddress((void**)&Agh,  g_Agh);
    cudaGetSymbolAddress((void**)&Agl,  g_Agl);
    cudaGetSymbolAddress((void**)&bg,   g_bg);
    cudaGetSymbolAddress((void**)&Fh,   g_Fh);
    cudaGetSymbolAddress((void**)&Fl,   g_Fl);

    const int GEMM_SMEM = (10240 * 2 + 8704 * 2) * 2;   // 75776 bytes
    cudaFuncSetAttribute(gemm_t<1, 1, 0, 0>, cudaFuncAttributeMaxDynamicSharedMemorySize, GEMM_SMEM);
    cudaFuncSetAttribute(gemm_t<0, 0, 1, 1>, cudaFuncAttributeMaxDynamicSharedMemorySize, GEMM_SMEM);
    cudaFuncSetAttribute(gemm_t<2, 1, 0, 0>, cudaFuncAttributeMaxDynamicSharedMemorySize, GEMM_SMEM);
    cudaFuncSetAttribute(gemm_t<0, 0, 1, 0>, cudaFuncAttributeMaxDynamicSharedMemorySize, GEMM_SMEM);

    const int pixBlocks = (BATCH * HW + 255) / 256;

    // 0. fold LN weights into split-bf16 A matrices
    prep_kernel<<<896, 96>>>(qkv_w, n1w, n1b, ffn1_w, ffn2_w, n2w, n2b, ffn_out_w);
    // 1. LN1 stats
    ln_stats<<<pixBlocks, 256>>>(x, mu, rs);
    // 2. qkv = Aq @ LN(x) + bq
    gemm_t<1, 1, 0, 0><<<dim3(512, 3, BATCH), 256, GEMM_SMEM>>>(Aqh, Aql, x, nullptr, qkv,
        bq, mu, rs, nullptr, nullptr, 288, 96, 96, 0, 96LL * HW, 0, 288LL * HW);
    // 3. depthwise 3x3
    dwconv3<<<dim3(8, 8, BATCH * 288), 256>>>(qkv, qkv_dw_w, qkvd);
    // 4. svp_q
    svp_kernel<<<pixBlocks, 256>>>(svp_fea, svp_w, svpq);
    // 5. row sums of squares
    sumsq_kernel<<<BATCH * 204, 256>>>(qkvd, svpq, ss);
    // 6. Gram partials
    gram_kernel<<<dim3(NSEG, 16), 672>>>(qkvd, svpq, gp);
    // 7. softmax + fold proj_out -> M[b]
    attnm_kernel<<<BATCH, 128>>>(gp, ss, temperature, proj_out_w, Mh, Ml);
    // 8. x2 = x + M_b @ v -> out, fused LN2 stats
    gemm_t<0, 0, 1, 1><<<dim3(512, 1, BATCH), 256, GEMM_SMEM>>>(Mh, Ml, qkvd + 192LL * HW, x, out,
        nullptr, nullptr, nullptr, mu, rs, 96, 96, 96, 9216, 288LL * HW, 96LL * HW, 96LL * HW);
    // 9. interleaved ffn1/ffn2 GEMM + fused dual-gate -> g (qkv buffer)
    gemm_t<2, 1, 0, 0><<<dim3(512, 4, BATCH), 256, GEMM_SMEM>>>(Agh, Agl, out, nullptr, qkv,
        bg, mu, rs, nullptr, nullptr, 512, 96, 96, 0, 96LL * HW, 0, 288LL * HW);
    // 10. out = out + ffn_out_w @ g
    gemm_t<0, 0, 1, 0><<<dim3(512, 1, BATCH), 256, GEMM_SMEM>>>(Fh, Fl, qkv, out, out,
        nullptr, nullptr, nullptr, nullptr, nullptr, 96, 255, 256, 0, 288LL * HW, 96LL * HW, 96LL * HW);
}

// round 10
// speedup vs baseline: 1.0578x; 1.0578x over previous
#include <cuda_runtime.h>
#include <cuda_bf16.h>
#include <math.h>
#include <stdint.h>

#define HW 65536
#define BATCH 4
#define NSEG 32
#define GCH 128
#define GPAD 140

// ---------------- static scratch ----------------
__device__ float g_qkv [(size_t)BATCH * 288 * HW];   // qkv pre-dwconv; later gated FFN 'g'
__device__ float g_qkvd[(size_t)BATCH * 288 * HW];   // qkv post-dwconv (q|k|v)
__device__ float g_svpq[(size_t)BATCH * 12  * HW];   // svp_q
__device__ float g_mu  [(size_t)BATCH * HW];
__device__ float g_rs  [(size_t)BATCH * HW];
__device__ float g_ss  [BATCH * 204];
__device__ float g_gp  [NSEG * 16 * 648];
__device__ __nv_bfloat16 g_Mh [BATCH * 96 * 96];
__device__ __nv_bfloat16 g_Ml [BATCH * 96 * 96];
__device__ __nv_bfloat16 g_Aqh[288 * 96];
__device__ __nv_bfloat16 g_Aql[288 * 96];
__device__ float g_bq  [288];
__device__ __nv_bfloat16 g_Agh[512 * 96];
__device__ __nv_bfloat16 g_Agl[512 * 96];
__device__ float g_bg  [512];
__device__ __nv_bfloat16 g_Fh [96 * 256];
__device__ __nv_bfloat16 g_Fl [96 * 256];

// ---------------- helpers ----------------
__device__ __forceinline__ void bsplit(float v, __nv_bfloat16& h, __nv_bfloat16& l) {
    h = __float2bfloat16(v);
    l = __float2bfloat16(v - __bfloat162float(h));
}
__device__ __forceinline__ void split2(float a, float b, uint32_t& h, uint32_t& l) {
    __nv_bfloat16 ha = __float2bfloat16(a), hb = __float2bfloat16(b);
    __nv_bfloat16 la = __float2bfloat16(a - __bfloat162float(ha));
    __nv_bfloat16 lb = __float2bfloat16(b - __bfloat162float(hb));
    __nv_bfloat162 hv(ha, hb), lv(la, lb);
    h = *(uint32_t*)&hv; l = *(uint32_t*)&lv;
}
__device__ __forceinline__ uint32_t s2u(const void* p) {
    return (uint32_t)__cvta_generic_to_shared(p);
}
__device__ __forceinline__ void ldsm4(uint32_t* r, uint32_t addr) {
    asm volatile("ldmatrix.sync.aligned.m8n8.x4.shared.b16 {%0,%1,%2,%3}, [%4];"
        : "=r"(r[0]), "=r"(r[1]), "=r"(r[2]), "=r"(r[3]) : "r"(addr));
}
__device__ __forceinline__ void ldsm4t(uint32_t* r, uint32_t addr) {
    asm volatile("ldmatrix.sync.aligned.m8n8.x4.trans.shared.b16 {%0,%1,%2,%3}, [%4];"
        : "=r"(r[0]), "=r"(r[1]), "=r"(r[2]), "=r"(r[3]) : "r"(addr));
}
__device__ __forceinline__ void mma_bf16(float* d, const uint32_t* a, const uint32_t* b) {
    asm volatile("mma.sync.aligned.m16n8k16.row.col.f32.bf16.bf16.f32 "
        "{%0,%1,%2,%3}, {%4,%5,%6,%7}, {%8,%9}, {%0,%1,%2,%3};"
        : "+f"(d[0]), "+f"(d[1]), "+f"(d[2]), "+f"(d[3])
        : "r"(a[0]), "r"(a[1]), "r"(a[2]), "r"(a[3]), "r"(b[0]), "r"(b[1]));
}
__device__ __forceinline__ void cp16(uint32_t saddr, const void* g, int sz) {
    asm volatile("cp.async.ca.shared.global [%0], [%1], 16, %2;"
        :: "r"(saddr), "l"(g), "r"(sz));
}
__device__ __forceinline__ void cp_commit() { asm volatile("cp.async.commit_group;"); }
__device__ __forceinline__ void cp_wait0()  { asm volatile("cp.async.wait_group 0;" ::: "memory"); }
__device__ __forceinline__ float gatef(float a, float bb) {
    float sig = 1.f / (1.f + expf(-bb));
    float gel = 0.5f * a * (1.f + erff(a * 0.70710678118654752f));
    return a * sig + bb * gel;
}

// ---------------- prep: fold LN weights, split to bf16 hi/lo ----------------
__global__ void prep_kernel(const float* __restrict__ qkv_w,
                            const float* __restrict__ n1w, const float* __restrict__ n1b,
                            const float* __restrict__ ffn1_w, const float* __restrict__ ffn2_w,
                            const float* __restrict__ n2w, const float* __restrict__ n2b,
                            const float* __restrict__ ffn_out_w) {
    int r = blockIdx.x;
    int k = threadIdx.x;  // 0..95
    __shared__ float red[96];
    if (r < 288) {
        float wv = qkv_w[r * 96 + k];
        bsplit(wv * n1w[k], g_Aqh[r * 96 + k], g_Aql[r * 96 + k]);
        red[k] = wv * n1b[k];
        __syncthreads();
        if (k == 0) { float s = 0.f; for (int j = 0; j < 96; j++) s += red[j]; g_bq[r] = s; }
    } else if (r < 800) {
        int c = r - 288;                  // 0..511
        int T = c >> 4, wi = c & 15;
        int g = T * 8 + (wi & 7);
        bool valid = (g < 255);
        const float* W = (wi < 8) ? ffn1_w : ffn2_w;
        float wv = valid ? W[g * 96 + k] : 0.f;
        bsplit(wv * n2w[k], g_Agh[c * 96 + k], g_Agl[c * 96 + k]);
        red[k] = wv * n2b[k];
        __syncthreads();
        if (k == 0) {
            float s = 0.f; for (int j = 0; j < 96; j++) s += red[j];
            if (valid) g_bg[(wi < 8 ? 0 : 256) + g] = s;
        }
    } else {
        int o = r - 800;                  // 0..95
        for (int kk = k; kk < 256; kk += 96) {
            float v = (kk < 255) ? ffn_out_w[o * 255 + kk] : 0.f;
            bsplit(v, g_Fh[o * 256 + kk], g_Fl[o * 256 + kk]);
        }
    }
}

// ---------------- LN stats (LN1 only; LN2 fused into gemm8 epilogue) ----------------
__global__ void ln_stats(const float* __restrict__ x, float* __restrict__ mu,
                         float* __restrict__ rs) {
    int i = blockIdx.x * blockDim.x + threadIdx.x;
    if (i >= BATCH * HW) return;
    int b = i >> 16, pix = i & 65535;
    const float* xp = x + (long long)b * 96 * HW + pix;
    float sum = 0.f, sq = 0.f;
    #pragma unroll 8
    for (int c = 0; c < 96; c++) {
        float v = xp[(long long)c * HW];
        sum += v; sq += v * v;
    }
    float m = sum * (1.f / 96.f);
    float var = sq * (1.f / 96.f) - m * m;
    mu[i] = m;
    rs[i] = rsqrtf(var + 1e-5f);
}

// ---------------- tensor-core GEMM: C[M,N=65536] = A[M,K]@B[K,N], split-bf16 ----------------
// BM=BN=128, BK=32, 256 threads (4x2 warps of 32x64). A via cp.async (row-major smem),
// B warp-per-k-row coalesced LDG.128 + uint2 STS.64 split-stash.
// EPI: 0 plain(+RESID), 1 +bias, 2 dual-gate. STATS: fused LN stats (needs gridDim.y==1,M=96).
template <int EPI, int LN, int RESID, int STATS>
__global__ __launch_bounds__(256) void gemm_t(
    const __nv_bfloat16* __restrict__ Ah, const __nv_bfloat16* __restrict__ Al,
    const float* __restrict__ B, const float* __restrict__ R, float* __restrict__ C,
    const float* __restrict__ bias,
    const float* __restrict__ mu, const float* __restrict__ rs,
    float* __restrict__ muo, float* __restrict__ rso,
    int M, int K, int Kpad,
    long long sA, long long sB, long long sR, long long sC)
{
    extern __shared__ __align__(16) char smem_raw[];
    __nv_bfloat16* Ash = (__nv_bfloat16*)smem_raw;   // [2][128][40]
    __nv_bfloat16* Asl = Ash + 10240;                // [2][128][40]
    __nv_bfloat16* Bsh = Asl + 10240;                // [2][32][136]
    __nv_bfloat16* Bsl = Bsh + 8704;                 // [2][32][136]

    Ah += (long long)blockIdx.z * sA;
    Al += (long long)blockIdx.z * sA;
    B  += (long long)blockIdx.z * sB;
    C  += (long long)blockIdx.z * sC;
    if (RESID) R += (long long)blockIdx.z * sR;
    if (LN) { mu += (long long)blockIdx.z * HW; rs += (long long)blockIdx.z * HW; }

    const int m_base = blockIdx.y * 128;
    const int n_base = blockIdx.x * 128;
    const int tid  = threadIdx.x;
    const int lane = tid & 31;
    const int warp = tid >> 5;
    const int wm = warp >> 1, wn = warp & 1;

    // A cp.async coords
    const int a_row = tid & 127;
    const int a_kc  = tid >> 7;         // kc = a_kc + 2j

    float4 m4, r4;
    if (LN) {
        m4 = *(const float4*)(mu + n_base + lane * 4);
        r4 = *(const float4*)(rs + n_base + lane * 4);
    }

    float acc[2][8][4];
    #pragma unroll
    for (int i = 0; i < 2; i++)
        #pragma unroll
        for (int j = 0; j < 8; j++)
            #pragma unroll
            for (int q = 0; q < 4; q++) acc[i][j][q] = 0.f;

    const int nst = (K + 31) >> 5;
    uint2 rbh[4], rbl[4];

    auto cpA = [&](int kg, int buf) {
        int grow = m_base + a_row;
        int sz = (grow < M) ? 16 : 0;
        long long base = (long long)(grow < M ? grow : 0) * Kpad + kg;
        #pragma unroll
        for (int j = 0; j < 2; j++) {
            int kc = a_kc + 2 * j;
            int soff = buf * 5120 + a_row * 40 + kc * 8;
            cp16(s2u(&Ash[soff]), Ah + base + kc * 8, sz);
            cp16(s2u(&Asl[soff]), Al + base + kc * 8, sz);
        }
    };
    // B: warp w loads k-rows w+8j, lane covers cols lane*4 (fully coalesced LDG.128)
    auto fetchB = [&](int kg) {
        #pragma unroll
        for (int j = 0; j < 4; j++) {
            int kb = kg + warp + 8 * j;
            float4 v = make_float4(0.f, 0.f, 0.f, 0.f);
            if (kb < K) {
                v = *(const float4*)(B + (long long)kb * HW + n_base + lane * 4);
                if (LN) {
                    v.x = (v.x - m4.x) * r4.x; v.y = (v.y - m4.y) * r4.y;
                    v.z = (v.z - m4.z) * r4.z; v.w = (v.w - m4.w) * r4.w;
                }
            }
            split2(v.x, v.y, rbh[j].x, rbl[j].x);
            split2(v.z, v.w, rbh[j].y, rbl[j].y);
        }
    };
    auto stashB = [&](int buf) {
        #pragma unroll
        for (int j = 0; j < 4; j++) {
            int kb = warp + 8 * j;
            *(uint2*)&Bsh[buf * 4352 + kb * 136 + lane * 4] = rbh[j];
            *(uint2*)&Bsl[buf * 4352 + kb * 136 + lane * 4] = rbl[j];
        }
    };

    // prologue
    cpA(0, 0);
    cp_commit();
    fetchB(0);
    stashB(0);
    cp_wait0();
    __syncthreads();

    // ldmatrix lane offsets
    const int a_r  = lane & 15;
    const int a_c  = (lane >> 4) << 3;
    const int b_r  = (lane & 7) + ((lane >> 3) & 1) * 8;
    const int b_c  = ((lane >> 4) & 1) * 8 + wn * 64;

    for (int s = 0; s < nst; s++) {
        int buf = s & 1;
        if (s + 1 < nst) {
            cpA((s + 1) * 32, buf ^ 1);
            cp_commit();
            fetchB((s + 1) * 32);
        }
        #pragma unroll
        for (int step = 0; step < 2; step++) {
            uint32_t ah[2][4], al[2][4];
            #pragma unroll
            for (int i = 0; i < 2; i++) {
                int off = buf * 5120 + (wm * 32 + i * 16 + a_r) * 40 + step * 16 + a_c;
                ldsm4(ah[i], s2u(&Ash[off]));
                ldsm4(al[i], s2u(&Asl[off]));
            }
            uint32_t bh[4][4], bl[4][4];
            #pragma unroll
            for (int jp = 0; jp < 4; jp++) {
                int off = buf * 4352 + (step * 16 + b_r) * 136 + b_c + jp * 16;
                ldsm4t(bh[jp], s2u(&Bsh[off]));
                ldsm4t(bl[jp], s2u(&Bsl[off]));
            }
            #pragma unroll
            for (int i = 0; i < 2; i++) {
                #pragma unroll
                for (int j = 0; j < 8; j++) {
                    int jp = j >> 1;
                    const uint32_t* bhp = (j & 1) ? bh[jp] + 2 : bh[jp];
                    const uint32_t* blp = (j & 1) ? bl[jp] + 2 : bl[jp];
                    mma_bf16(acc[i][j], ah[i], bhp);
                    mma_bf16(acc[i][j], ah[i], blp);
                    mma_bf16(acc[i][j], al[i], bhp);
                }
            }
        }
        if (s + 1 < nst) {
            stashB(buf ^ 1);
            cp_wait0();
        }
        __syncthreads();
    }

    // ---------------- epilogue ----------------
    float ls[16], ls2[16];
    if (STATS) {
        #pragma unroll
        for (int e = 0; e < 16; e++) { ls[e] = 0.f; ls2[e] = 0.f; }
    }

    if (EPI == 2) {
        #pragma unroll
        for (int i = 0; i < 2; i++) {
            int T = (m_base >> 4) + wm * 2 + i;
            int g = T * 8 + (lane >> 2);
            if (g < 255) {
                float b1 = bias[g], b2 = bias[256 + g];
                #pragma unroll
                for (int j = 0; j < 8; j++) {
                    int col = n_base + wn * 64 + j * 8 + 2 * (lane & 3);
                    float2 v;
                    v.x = gatef(acc[i][j][0] + b1, acc[i][j][2] + b2);
                    v.y = gatef(acc[i][j][1] + b1, acc[i][j][3] + b2);
                    *(float2*)(C + (long long)g * HW + col) = v;
                }
            }
        }
    } else {
        #pragma unroll
        for (int i = 0; i < 2; i++) {
            int r0 = m_base + wm * 32 + i * 16 + (lane >> 2);
            int r1 = r0 + 8;
            float bv0 = 0.f, bv1 = 0.f;
            if (EPI == 1) {
                if (r0 < M) bv0 = bias[r0];
                if (r1 < M) bv1 = bias[r1];
            }
            #pragma unroll
            for (int j = 0; j < 8; j++) {
                int col = n_base + wn * 64 + j * 8 + 2 * (lane & 3);
                if (r0 < M) {
                    float2 v = make_float2(acc[i][j][0] + bv0, acc[i][j][1] + bv0);
                    long long o = (long long)r0 * HW + col;
                    if (RESID) { float2 rr = *(const float2*)(R + o); v.x += rr.x; v.y += rr.y; }
                    *(float2*)(C + o) = v;
                    if (STATS) {
                        ls[2 * j] += v.x; ls[2 * j + 1] += v.y;
                        ls2[2 * j] += v.x * v.x; ls2[2 * j + 1] += v.y * v.y;
                    }
                }
                if (r1 < M) {
                    float2 v = make_float2(acc[i][j][2] + bv1, acc[i][j][3] + bv1);
                    long long o = (long long)r1 * HW + col;
                    if (RESID) { float2 rr = *(const float2*)(R + o); v.x += rr.x; v.y += rr.y; }
                    *(float2*)(C + o) = v;
                    if (STATS) {
                        ls[2 * j] += v.x; ls[2 * j + 1] += v.y;
                        ls2[2 * j] += v.x * v.x; ls2[2 * j + 1] += v.y * v.y;
                    }
                }
            }
        }
    }

    if (STATS) {
        __syncthreads();
        float* sstat = (float*)smem_raw;   // [0..127]=sum, [128..255]=sumsq
        sstat[tid] = 0.f;
        __syncthreads();
        if (wm < 3) {   // M=96: only warps wm 0..2 hold valid rows
            #pragma unroll
            for (int o = 16; o >= 4; o >>= 1) {
                #pragma unroll
                for (int e = 0; e < 16; e++) {
                    ls[e]  += __shfl_down_sync(0xffffffffu, ls[e],  o);
                    ls2[e] += __shfl_down_sync(0xffffffffu, ls2[e], o);
                }
            }
            if (lane < 4) {
                #pragma unroll
                for (int e = 0; e < 16; e++) {
                    int j = e >> 1, q = e & 1;
                    int nl = wn * 64 + j * 8 + 2 * lane + q;
                    atomicAdd(&sstat[nl], ls[e]);
                    atomicAdd(&sstat[128 + nl], ls2[e]);
                }
            }
        }
        __syncthreads();
        if (tid < 128) {
            float sm = sstat[tid] * (1.f / 96.f);
            float sq = sstat[tid + 128] * (1.f / 96.f);
            float var = sq - sm * sm;
            muo[(long long)blockIdx.z * HW + n_base + tid] = sm;
            rso[(long long)blockIdx.z * HW + n_base + tid] = rsqrtf(var + 1e-5f);
        }
    }
}

// ---------------- 3x3 depthwise conv: 32x32 tile, float4 I/O ----------------
__global__ __launch_bounds__(256) void dwconv3(const float* __restrict__ in,
                                               const float* __restrict__ w,
                                               float* __restrict__ out) {
    int zc = blockIdx.z;
    int c = zc % 288;
    const float* src = in  + (long long)zc * HW;
    float*       dst = out + (long long)zc * HW;
    int ox = blockIdx.x * 32, oy = blockIdx.y * 32;
    __shared__ float s[34][40];    // col c <-> gx = ox-4+c ; needed cols 3..36
    int tid = threadIdx.x;
    #pragma unroll
    for (int j = 0; j < 2; j++) {
        int sl = tid + j * 256;
        if (sl < 340) {
            int r = sl / 10, q = sl - r * 10;
            int gy = oy + r - 1, gx = ox - 4 + q * 4;
            float4 v = make_float4(0.f, 0.f, 0.f, 0.f);
            if (gy >= 0 && gy < 256 && gx >= 0 && gx <= 252)
                v = *(const float4*)(src + gy * 256 + gx);
            *(float4*)&s[r][q * 4] = v;
        }
    }
    __syncthreads();
    const float* wc = w + c * 9;
    float w00 = wc[0], w01 = wc[1], w02 = wc[2];
    float w10 = wc[3], w11 = wc[4], w12 = wc[5];
    float w20 = wc[6], w21 = wc[7], w22 = wc[8];
    int row  = tid >> 3;           // 0..31
    int colq = (tid & 7) * 4;      // 0..28
    float v[3][6];
    #pragma unroll
    for (int dr = 0; dr < 3; dr++) {
        float4 m = *(const float4*)&s[row + dr][colq + 4];
        v[dr][0] = s[row + dr][colq + 3];
        v[dr][1] = m.x; v[dr][2] = m.y; v[dr][3] = m.z; v[dr][4] = m.w;
        v[dr][5] = s[row + dr][colq + 8];
    }
    float4 o;
    float* op = (float*)&o;
    #pragma unroll
    for (int t = 0; t < 4; t++) {
        op[t] = w00 * v[0][t] + w01 * v[0][t + 1] + w02 * v[0][t + 2]
              + w10 * v[1][t] + w11 * v[1][t + 1] + w12 * v[1][t + 2]
              + w20 * v[2][t] + w21 * v[2][t + 1] + w22 * v[2][t + 2];
    }
    *(float4*)(dst + (oy + row) * 256 + ox + colq) = o;
}

// ---------------- svp 1x1 conv ----------------
__global__ void svp_kernel(const float* __restrict__ fea, const float* __restrict__ w,
                           float* __restrict__ out) {
    int i = blockIdx.x * blockDim.x + threadIdx.x;
    if (i >= BATCH * HW) return;
    int b = i >> 16, pix = i & 65535;
    const float* f = fea + (long long)b * 3 * HW + pix;
    float f0 = f[0], f1 = f[HW], f2 = f[2 * HW];
    float* o = out + (long long)b * 12 * HW + pix;
    #pragma unroll
    for (int r = 0; r < 12; r++)
        o[(long long)r * HW] = w[r * 3] * f0 + w[r * 3 + 1] * f1 + w[r * 3 + 2] * f2;
}

// ---------------- per-row sum of squares ----------------
__global__ void sumsq_kernel(const float* __restrict__ qkvd, const float* __restrict__ svpq,
                             float* __restrict__ ss) {
    int bid = blockIdx.x;
    int b = bid / 204, r = bid % 204;
    const float* row = (r < 192) ? qkvd + ((long long)b * 288 + r) * HW
                                 : svpq + ((long long)b * 12 + (r - 192)) * HW;
    float acc = 0.f;
    for (int i = threadIdx.x * 4; i < HW; i += blockDim.x * 4) {
        float4 v = *(const float4*)(row + i);
        acc += v.x * v.x + v.y * v.y + v.z * v.z + v.w * v.w;
    }
    __shared__ float red[256];
    red[threadIdx.x] = acc;
    __syncthreads();
    for (int st = 128; st > 0; st >>= 1) {
        if (threadIdx.x < st) red[threadIdx.x] += red[threadIdx.x + st];
        __syncthreads();
    }
    if (threadIdx.x == 0) ss[bid] = red[0];
}

// ---------------- Gram partials ----------------
__global__ __launch_bounds__(672) void gram_kernel(const float* __restrict__ qkvd,
                                                   const float* __restrict__ svpq,
                                                   float* __restrict__ gp) {
    __shared__ float qs[27 * GPAD];
    __shared__ float ks[24 * GPAD];
    int seg = blockIdx.x;
    int bh  = blockIdx.y;
    int b = bh >> 2, h = bh & 3;
    int tid = threadIdx.x;
    int c = tid / 24, d = tid % 24;
    bool active = tid < 648;
    long long segoff = (long long)seg * (HW / NSEG);
    float acc = 0.f;

    for (int ch = 0; ch < HW / NSEG; ch += GCH) {
        for (int i = tid; i < 51 * (GCH / 4); i += 672) {
            int row = i / (GCH / 4), col4 = i % (GCH / 4);
            const float* src;
            float* dstb;
            if (row < 27) {
                src = (row < 24) ? qkvd + ((long long)b * 288 + h * 24 + row) * HW
                                 : svpq + ((long long)b * 12 + h * 3 + (row - 24)) * HW;
                dstb = qs + row * GPAD;
            } else {
                int rr = row - 27;
                src = qkvd + ((long long)b * 288 + 96 + h * 24 + rr) * HW;
                dstb = ks + rr * GPAD;
            }
            *(float4*)(dstb + col4 * 4) = *(const float4*)(src + segoff + ch + col4 * 4);
        }
        __syncthreads();
        if (active) {
            const float4* q4 = (const float4*)(qs + c * GPAD);
            const float4* k4 = (const float4*)(ks + d * GPAD);
            #pragma unroll 8
            for (int p = 0; p < GCH / 4; p++) {
                float4 qv = q4[p], kv = k4[p];
                acc += qv.x * kv.x + qv.y * kv.y + qv.z * kv.z + qv.w * kv.w;
            }
        }
        __syncthreads();
    }
    if (active) gp[((long long)seg * 16 + bh) * 648 + tid] = acc;
}

// ---------------- attn softmax + fold proj_out -> M[b] (bf16 split) ----------------
__global__ void attnm_kernel(const float* __restrict__ gp, const float* __restrict__ ss,
                             const float* __restrict__ temp, const float* __restrict__ projw,
                             __nv_bfloat16* __restrict__ Mh, __nv_bfloat16* __restrict__ Ml) {
    int b = blockIdx.x;
    __shared__ float attn_s[4][27][24];
    int tid = threadIdx.x;
    if (tid < 108) {
        int h = tid / 27, c = tid % 27;
        float ssq = (c < 24) ? ss[b * 204 + h * 24 + c]
                             : ss[b * 204 + 192 + h * 3 + (c - 24)];
        float nq = fmaxf(sqrtf(ssq), 1e-12f);
        float t = temp[h];
        float row[24];
        #pragma unroll
        for (int d = 0; d < 24; d++) {
            float g = 0.f;
            for (int s = 0; s < NSEG; s++)
                g += gp[((long long)s * 16 + b * 4 + h) * 648 + c * 24 + d];
            float nk = fmaxf(sqrtf(ss[b * 204 + 96 + h * 24 + d]), 1e-12f);
            row[d] = g * t / (nq * nk);
        }
        float mx = row[0];
        #pragma unroll
        for (int d = 1; d < 24; d++) mx = fmaxf(mx, row[d]);
        float sum = 0.f;
        #pragma unroll
        for (int d = 0; d < 24; d++) { row[d] = expf(row[d] - mx); sum += row[d]; }
        float inv = 1.f / sum;
        #pragma unroll
        for (int d = 0; d < 24; d++) attn_s[h][c][d] = row[d] * inv;
    }
    __syncthreads();
    for (int e = tid; e < 96 * 96; e += blockDim.x) {
        int o = e / 96, col = e % 96;
        int h = col / 24, d = col % 24;
        float s = 0.f;
        #pragma unroll
        for (int c = 0; c < 27; c++)
            s += projw[o * 108 + h * 27 + c] * attn_s[h][c][d];
        bsplit(s, Mh[b * 9216 + e], Ml[b * 9216 + e]);
    }
}

// ---------------- launch ----------------
extern "C" void kernel_launch(void* const* d_in, const int* in_sizes, int n_in,
                              void* d_out, int out_size) {
    const float* x           = (const float*)d_in[0];
    const float* svp_fea     = (const float*)d_in[1];
    const float* n1w         = (const float*)d_in[2];
    const float* n1b         = (const float*)d_in[3];
    const float* qkv_w       = (const float*)d_in[4];
    const float* qkv_dw_w    = (const float*)d_in[5];
    const float* svp_w       = (const float*)d_in[6];
    const float* temperature = (const float*)d_in[7];
    const float* proj_out_w  = (const float*)d_in[8];
    const float* n2w         = (const float*)d_in[9];
    const float* n2b         = (const float*)d_in[10];
    const float* ffn1_w      = (const float*)d_in[11];
    const float* ffn2_w      = (const float*)d_in[12];
    const float* ffn_out_w   = (const float*)d_in[13];
    float* out = (float*)d_out;

    float *qkv, *qkvd, *svpq, *mu, *rs, *ss, *gp, *bq, *bg;
    __nv_bfloat16 *Mh, *Ml, *Aqh, *Aql, *Agh, *Agl, *Fh, *Fl;
    cudaGetSymbolAddress((void**)&qkv,  g_qkv);
    cudaGetSymbolAddress((void**)&qkvd, g_qkvd);
    cudaGetSymbolAddress((void**)&svpq, g_svpq);
    cudaGetSymbolAddress((void**)&mu,   g_mu);
    cudaGetSymbolAddress((void**)&rs,   g_rs);
    cudaGetSymbolAddress((void**)&ss,   g_ss);
    cudaGetSymbolAddress((void**)&gp,   g_gp);
    cudaGetSymbolAddress((void**)&Mh,   g_Mh);
    cudaGetSymbolAddress((void**)&Ml,   g_Ml);
    cudaGetSymbolAddress((void**)&Aqh,  g_Aqh);
    cudaGetSymbolAddress((void**)&Aql,  g_Aql);
    cudaGetSymbolAddress((void**)&bq,   g_bq);
    cudaGetSymbolAddress((void**)&Agh,  g_Agh);
    cudaGetSymbolAddress((void**)&Agl,  g_Agl);
    cudaGetSymbolAddress((void**)&bg,   g_bg);
    cudaGetSymbolAddress((void**)&Fh,   g_Fh);
    cudaGetSymbolAddress((void**)&Fl,   g_Fl);

    const int GEMM_SMEM = (10240 * 2 + 8704 * 2) * 2;   // 75776 bytes
    cudaFuncSetAttribute(gemm_t<1, 1, 0, 0>, cudaFuncAttributeMaxDynamicSharedMemorySize, GEMM_SMEM);
    cudaFuncSetAttribute(gemm_t<0, 0, 1, 1>, cudaFuncAttributeMaxDynamicSharedMemorySize, GEMM_SMEM);
    cudaFuncSetAttribute(gemm_t<2, 1, 0, 0>, cudaFuncAttributeMaxDynamicSharedMemorySize, GEMM_SMEM);
    cudaFuncSetAttribute(gemm_t<0, 0, 1, 0>, cudaFuncAttributeMaxDynamicSharedMemorySize, GEMM_SMEM);

    const int pixBlocks = (BATCH * HW + 255) / 256;

    // 0. fold LN weights into split-bf16 A matrices
    prep_kernel<<<896, 96>>>(qkv_w, n1w, n1b, ffn1_w, ffn2_w, n2w, n2b, ffn_out_w);
    // 1. LN1 stats
    ln_stats<<<pixBlocks, 256>>>(x, mu, rs);
    // 2. qkv = Aq @ LN(x) + bq
    gemm_t<1, 1, 0, 0><<<dim3(512, 3, BATCH), 256, GEMM_SMEM>>>(Aqh, Aql, x, nullptr, qkv,
        bq, mu, rs, nullptr, nullptr, 288, 96, 96, 0, 96LL * HW, 0, 288LL * HW);
    // 3. depthwise 3x3
    dwconv3<<<dim3(8, 8, BATCH * 288), 256>>>(qkv, qkv_dw_w, qkvd);
    // 4. svp_q
    svp_kernel<<<pixBlocks, 256>>>(svp_fea, svp_w, svpq);
    // 5. row sums of squares
    sumsq_kernel<<<BATCH * 204, 256>>>(qkvd, svpq, ss);
    // 6. Gram partials
    gram_kernel<<<dim3(NSEG, 16), 672>>>(qkvd, svpq, gp);
    // 7. softmax + fold proj_out -> M[b]
    attnm_kernel<<<BATCH, 128>>>(gp, ss, temperature, proj_out_w, Mh, Ml);
    // 8. x2 = x + M_b @ v -> out, fused LN2 stats
    gemm_t<0, 0, 1, 1><<<dim3(512, 1, BATCH), 256, GEMM_SMEM>>>(Mh, Ml, qkvd + 192LL * HW, x, out,
        nullptr, nullptr, nullptr, mu, rs, 96, 96, 96, 9216, 288LL * HW, 96LL * HW, 96LL * HW);
    // 9. interleaved ffn1/ffn2 GEMM + fused dual-gate -> g (qkv buffer)
    gemm_t<2, 1, 0, 0><<<dim3(512, 4, BATCH), 256, GEMM_SMEM>>>(Agh, Agl, out, nullptr, qkv,
        bg, mu, rs, nullptr, nullptr, 512, 96, 96, 0, 96LL * HW, 0, 288LL * HW);
    // 10. out = out + ffn_out_w @ g
    gemm_t<0, 0, 1, 0><<<dim3(512, 1, BATCH), 256, GEMM_SMEM>>>(Fh, Fl, qkv, out, out,
        nullptr, nullptr, nullptr, nullptr, nullptr, 96, 255, 256, 0, 288LL * HW, 96LL * HW, 96LL * HW);
}

// round 11
// speedup vs baseline: 1.0787x; 1.0198x over previous
#include <cuda_runtime.h>
#include <cuda_bf16.h>
#include <math.h>
#include <stdint.h>

#define HW 65536
#define BATCH 4
#define NSEG 32
#define GCH 128
#define GPAD 140

// ---------------- static scratch ----------------
__device__ float g_qkv [(size_t)BATCH * 288 * HW];   // qkv pre-dwconv; later gated FFN 'g'
__device__ float g_qkvd[(size_t)BATCH * 288 * HW];   // qkv post-dwconv (q|k|v)
__device__ float g_svpq[(size_t)BATCH * 12  * HW];   // svp_q
__device__ float g_mu  [(size_t)BATCH * HW];
__device__ float g_rs  [(size_t)BATCH * HW];
__device__ float g_ss  [BATCH * 204];
__device__ float g_gp  [NSEG * 16 * 648];
__device__ __nv_bfloat16 g_Mh [BATCH * 96 * 96];
__device__ __nv_bfloat16 g_Ml [BATCH * 96 * 96];
__device__ __nv_bfloat16 g_Aqh[288 * 96];
__device__ __nv_bfloat16 g_Aql[288 * 96];
__device__ float g_bq  [288];
__device__ __nv_bfloat16 g_Agh[512 * 96];
__device__ __nv_bfloat16 g_Agl[512 * 96];
__device__ float g_bg  [512];
__device__ __nv_bfloat16 g_Fh [96 * 256];
__device__ __nv_bfloat16 g_Fl [96 * 256];

// ---------------- helpers ----------------
__device__ __forceinline__ void bsplit(float v, __nv_bfloat16& h, __nv_bfloat16& l) {
    h = __float2bfloat16(v);
    l = __float2bfloat16(v - __bfloat162float(h));
}
__device__ __forceinline__ void split2(float a, float b, uint32_t& h, uint32_t& l) {
    __nv_bfloat16 ha = __float2bfloat16(a), hb = __float2bfloat16(b);
    __nv_bfloat16 la = __float2bfloat16(a - __bfloat162float(ha));
    __nv_bfloat16 lb = __float2bfloat16(b - __bfloat162float(hb));
    __nv_bfloat162 hv(ha, hb), lv(la, lb);
    h = *(uint32_t*)&hv; l = *(uint32_t*)&lv;
}
__device__ __forceinline__ uint32_t s2u(const void* p) {
    return (uint32_t)__cvta_generic_to_shared(p);
}
__device__ __forceinline__ void ldsm4t(uint32_t* r, uint32_t addr) {
    asm volatile("ldmatrix.sync.aligned.m8n8.x4.trans.shared.b16 {%0,%1,%2,%3}, [%4];"
        : "=r"(r[0]), "=r"(r[1]), "=r"(r[2]), "=r"(r[3]) : "r"(addr));
}
__device__ __forceinline__ void mma_bf16(float* d, const uint32_t* a, const uint32_t* b) {
    asm volatile("mma.sync.aligned.m16n8k16.row.col.f32.bf16.bf16.f32 "
        "{%0,%1,%2,%3}, {%4,%5,%6,%7}, {%8,%9}, {%0,%1,%2,%3};"
        : "+f"(d[0]), "+f"(d[1]), "+f"(d[2]), "+f"(d[3])
        : "r"(a[0]), "r"(a[1]), "r"(a[2]), "r"(a[3]), "r"(b[0]), "r"(b[1]));
}
__device__ __forceinline__ float gatef(float a, float bb) {
    float sig = 1.f / (1.f + expf(-bb));
    float gel = 0.5f * a * (1.f + erff(a * 0.70710678118654752f));
    return a * sig + bb * gel;
}

// ---------------- prep: fold LN weights, split to bf16 hi/lo, zero ss ----------------
__global__ void prep_kernel(const float* __restrict__ qkv_w,
                            const float* __restrict__ n1w, const float* __restrict__ n1b,
                            const float* __restrict__ ffn1_w, const float* __restrict__ ffn2_w,
                            const float* __restrict__ n2w, const float* __restrict__ n2b,
                            const float* __restrict__ ffn_out_w, float* __restrict__ ss) {
    int r = blockIdx.x;
    int k = threadIdx.x;  // 0..95
    __shared__ float red[96];
    if (r < 288) {
        float wv = qkv_w[r * 96 + k];
        bsplit(wv * n1w[k], g_Aqh[r * 96 + k], g_Aql[r * 96 + k]);
        red[k] = wv * n1b[k];
        __syncthreads();
        if (k == 0) { float s = 0.f; for (int j = 0; j < 96; j++) s += red[j]; g_bq[r] = s; }
    } else if (r < 800) {
        int c = r - 288;                  // 0..511
        int T = c >> 4, wi = c & 15;
        int g = T * 8 + (wi & 7);
        bool valid = (g < 255);
        const float* W = (wi < 8) ? ffn1_w : ffn2_w;
        float wv = valid ? W[g * 96 + k] : 0.f;
        bsplit(wv * n2w[k], g_Agh[c * 96 + k], g_Agl[c * 96 + k]);
        red[k] = wv * n2b[k];
        __syncthreads();
        if (k == 0) {
            float s = 0.f; for (int j = 0; j < 96; j++) s += red[j];
            if (valid) g_bg[(wi < 8 ? 0 : 256) + g] = s;
        }
    } else if (r < 896) {
        int o = r - 800;                  // 0..95
        for (int kk = k; kk < 256; kk += 96) {
            float v = (kk < 255) ? ffn_out_w[o * 255 + kk] : 0.f;
            bsplit(v, g_Fh[o * 256 + kk], g_Fl[o * 256 + kk]);
        }
    } else {
        for (int j = k; j < BATCH * 204; j += 96) ss[j] = 0.f;
    }
}

// ---------------- LN stats (LN1 only; LN2 fused into gemm8 epilogue) ----------------
__global__ void ln_stats(const float* __restrict__ x, float* __restrict__ mu,
                         float* __restrict__ rs) {
    int i = blockIdx.x * blockDim.x + threadIdx.x;
    if (i >= BATCH * HW) return;
    int b = i >> 16, pix = i & 65535;
    const float* xp = x + (long long)b * 96 * HW + pix;
    float sum = 0.f, sq = 0.f;
    #pragma unroll 8
    for (int c = 0; c < 96; c++) {
        float v = xp[(long long)c * HW];
        sum += v; sq += v * v;
    }
    float m = sum * (1.f / 96.f);
    float var = sq * (1.f / 96.f) - m * m;
    mu[i] = m;
    rs[i] = rsqrtf(var + 1e-5f);
}

// ---------------- tensor-core GEMM (R7 core): C[M,65536]=A[M,K]@B, split-bf16 ----------------
// BM=BN=128, BK=32, 256 threads (4x2 warps of 32x64). k-major smem, trans ldmatrix.
// EPI: 0 plain(+RESID), 1 +bias, 2 dual-gate. STATS: fused LN stats (gridDim.y==1, M=96).
template <int EPI, int LN, int RESID, int STATS>
__global__ __launch_bounds__(256) void gemm_t(
    const __nv_bfloat16* __restrict__ Ah, const __nv_bfloat16* __restrict__ Al,
    const float* __restrict__ B, const float* __restrict__ R, float* __restrict__ C,
    const float* __restrict__ bias,
    const float* __restrict__ mu, const float* __restrict__ rs,
    float* __restrict__ muo, float* __restrict__ rso,
    int M, int K, int Kpad,
    long long sA, long long sB, long long sR, long long sC)
{
    extern __shared__ __align__(16) char smem_raw[];
    __nv_bfloat16* Ash = (__nv_bfloat16*)smem_raw;       // [2][32][136]
    __nv_bfloat16* Asl = Ash + 2 * 4352;
    __nv_bfloat16* Bsh = Asl + 2 * 4352;
    __nv_bfloat16* Bsl = Bsh + 2 * 4352;

    Ah += (long long)blockIdx.z * sA;
    Al += (long long)blockIdx.z * sA;
    B  += (long long)blockIdx.z * sB;
    C  += (long long)blockIdx.z * sC;
    if (RESID) R += (long long)blockIdx.z * sR;
    if (LN) { mu += (long long)blockIdx.z * HW; rs += (long long)blockIdx.z * HW; }

    const int m_base = blockIdx.y * 128;
    const int n_base = blockIdx.x * 128;
    const int tid  = threadIdx.x;
    const int lane = tid & 31;
    const int warp = tid >> 5;
    const int wm = warp >> 1, wn = warp & 1;

    // loader coords
    const int bcol = (tid & 31) * 4;   // B col (fixed)
    const int bk0  = tid >> 5;         // B k row base (+8j)
    const int am   = tid & 127;        // A m (fixed)
    const int akc0 = tid >> 7;         // A k-chunk base (+2j), chunk = 8 bf16

    float4 m4, r4;
    if (LN) {
        m4 = *(const float4*)(mu + n_base + bcol);
        r4 = *(const float4*)(rs + n_base + bcol);
    }

    float acc[2][8][4];
    #pragma unroll
    for (int i = 0; i < 2; i++)
        #pragma unroll
        for (int j = 0; j < 8; j++)
            #pragma unroll
            for (int q = 0; q < 4; q++) acc[i][j][q] = 0.f;

    const int nst = (K + 31) >> 5;
    uint4 rgah[2], rgal[2];
    float4 rgb[4];

    // ldmatrix lane-derived offsets
    const int a_row = (lane & 7) + ((lane >> 4) & 1) * 8;
    const int a_col = ((lane >> 3) & 1) * 8;
    const int b_row = (lane & 7) + ((lane >> 3) & 1) * 8;
    const int b_col = ((lane >> 4) & 1) * 8 + wn * 64;

    auto fetch = [&](int kg) {
        #pragma unroll
        for (int j = 0; j < 2; j++) {
            int kc = akc0 + 2 * j;
            int grow = m_base + am;
            if (grow < M) {
                long long off = (long long)grow * Kpad + kg + kc * 8;
                rgah[j] = *(const uint4*)(Ah + off);
                rgal[j] = *(const uint4*)(Al + off);
            } else {
                rgah[j] = make_uint4(0, 0, 0, 0);
                rgal[j] = make_uint4(0, 0, 0, 0);
            }
        }
        #pragma unroll
        for (int j = 0; j < 4; j++) {
            int kb = kg + bk0 + 8 * j;
            if (kb < K) {
                float4 v = *(const float4*)(B + (long long)kb * HW + n_base + bcol);
                if (LN) {
                    v.x = (v.x - m4.x) * r4.x; v.y = (v.y - m4.y) * r4.y;
                    v.z = (v.z - m4.z) * r4.z; v.w = (v.w - m4.w) * r4.w;
                }
                rgb[j] = v;
            } else {
                rgb[j] = make_float4(0.f, 0.f, 0.f, 0.f);
            }
        }
    };
    auto stash = [&](int buf) {
        int base = buf * 4352;
        #pragma unroll
        for (int j = 0; j < 2; j++) {
            int kb = (akc0 + 2 * j) * 8;
            const __nv_bfloat16* ph = (const __nv_bfloat16*)&rgah[j];
            const __nv_bfloat16* pl = (const __nv_bfloat16*)&rgal[j];
            #pragma unroll
            for (int rr = 0; rr < 8; rr++) {
                Ash[base + (kb + rr) * 136 + am] = ph[rr];
                Asl[base + (kb + rr) * 136 + am] = pl[rr];
            }
        }
        #pragma unroll
        for (int j = 0; j < 4; j++) {
            int kb = bk0 + 8 * j;
            uint2 h2, l2;
            split2(rgb[j].x, rgb[j].y, h2.x, l2.x);
            split2(rgb[j].z, rgb[j].w, h2.y, l2.y);
            *(uint2*)&Bsh[base + kb * 136 + bcol] = h2;
            *(uint2*)&Bsl[base + kb * 136 + bcol] = l2;
        }
    };

    fetch(0);
    stash(0);
    __syncthreads();

    for (int s = 0; s < nst; s++) {
        int buf = s & 1;
        if (s + 1 < nst) fetch((s + 1) * 32);

        int base = buf * 4352;
        #pragma unroll
        for (int step = 0; step < 2; step++) {
            int k0 = step * 16;
            uint32_t ah[2][4], al[2][4];
            #pragma unroll
            for (int i = 0; i < 2; i++) {
                int col = wm * 32 + i * 16 + a_col;
                int off = base + (k0 + a_row) * 136 + col;
                ldsm4t(ah[i], s2u(&Ash[off]));
                ldsm4t(al[i], s2u(&Asl[off]));
            }
            uint32_t bh[4][4], bl[4][4];
            #pragma unroll
            for (int jp = 0; jp < 4; jp++) {
                int col = b_col + jp * 16;
                int off = base + (k0 + b_row) * 136 + col;
                ldsm4t(bh[jp], s2u(&Bsh[off]));
                ldsm4t(bl[jp], s2u(&Bsl[off]));
            }
            #pragma unroll
            for (int i = 0; i < 2; i++) {
                #pragma unroll
                for (int j = 0; j < 8; j++) {
                    int jp = j >> 1;
                    const uint32_t* bhp = (j & 1) ? bh[jp] + 2 : bh[jp];
                    const uint32_t* blp = (j & 1) ? bl[jp] + 2 : bl[jp];
                    mma_bf16(acc[i][j], ah[i], bhp);
                    mma_bf16(acc[i][j], ah[i], blp);
                    mma_bf16(acc[i][j], al[i], bhp);
                }
            }
        }
        if (s + 1 < nst) stash(buf ^ 1);
        __syncthreads();
    }

    // ---------------- epilogue ----------------
    float ls[16], ls2[16];
    if (STATS) {
        #pragma unroll
        for (int e = 0; e < 16; e++) { ls[e] = 0.f; ls2[e] = 0.f; }
    }

    if (EPI == 2) {
        #pragma unroll
        for (int i = 0; i < 2; i++) {
            int T = (m_base >> 4) + wm * 2 + i;
            int g = T * 8 + (lane >> 2);
            if (g < 255) {
                float b1 = bias[g], b2 = bias[256 + g];
                #pragma unroll
                for (int j = 0; j < 8; j++) {
                    int col = n_base + wn * 64 + j * 8 + 2 * (lane & 3);
                    float2 v;
                    v.x = gatef(acc[i][j][0] + b1, acc[i][j][2] + b2);
                    v.y = gatef(acc[i][j][1] + b1, acc[i][j][3] + b2);
                    *(float2*)(C + (long long)g * HW + col) = v;
                }
            }
        }
    } else {
        #pragma unroll
        for (int i = 0; i < 2; i++) {
            int r0 = m_base + wm * 32 + i * 16 + (lane >> 2);
            int r1 = r0 + 8;
            float bv0 = 0.f, bv1 = 0.f;
            if (EPI == 1) {
                if (r0 < M) bv0 = bias[r0];
                if (r1 < M) bv1 = bias[r1];
            }
            #pragma unroll
            for (int j = 0; j < 8; j++) {
                int col = n_base + wn * 64 + j * 8 + 2 * (lane & 3);
                if (r0 < M) {
                    float2 v = make_float2(acc[i][j][0] + bv0, acc[i][j][1] + bv0);
                    long long o = (long long)r0 * HW + col;
                    if (RESID) { float2 rr = *(const float2*)(R + o); v.x += rr.x; v.y += rr.y; }
                    *(float2*)(C + o) = v;
                    if (STATS) {
                        ls[2 * j] += v.x; ls[2 * j + 1] += v.y;
                        ls2[2 * j] += v.x * v.x; ls2[2 * j + 1] += v.y * v.y;
                    }
                }
                if (r1 < M) {
                    float2 v = make_float2(acc[i][j][2] + bv1, acc[i][j][3] + bv1);
                    long long o = (long long)r1 * HW + col;
                    if (RESID) { float2 rr = *(const float2*)(R + o); v.x += rr.x; v.y += rr.y; }
                    *(float2*)(C + o) = v;
                    if (STATS) {
                        ls[2 * j] += v.x; ls[2 * j + 1] += v.y;
                        ls2[2 * j] += v.x * v.x; ls2[2 * j + 1] += v.y * v.y;
                    }
                }
            }
        }
    }

    if (STATS) {
        __syncthreads();
        float* sstat = (float*)smem_raw;   // [0..127]=sum, [128..255]=sumsq
        sstat[tid] = 0.f;
        __syncthreads();
        if (wm < 3) {   // M=96: only warps wm 0..2 hold valid rows
            #pragma unroll
            for (int o = 16; o >= 4; o >>= 1) {
                #pragma unroll
                for (int e = 0; e < 16; e++) {
                    ls[e]  += __shfl_down_sync(0xffffffffu, ls[e],  o);
                    ls2[e] += __shfl_down_sync(0xffffffffu, ls2[e], o);
                }
            }
            if (lane < 4) {
                #pragma unroll
                for (int e = 0; e < 16; e++) {
                    int j = e >> 1, q = e & 1;
                    int nl = wn * 64 + j * 8 + 2 * lane + q;
                    atomicAdd(&sstat[nl], ls[e]);
                    atomicAdd(&sstat[128 + nl], ls2[e]);
                }
            }
        }
        __syncthreads();
        if (tid < 128) {
            float sm = sstat[tid] * (1.f / 96.f);
            float sq = sstat[tid + 128] * (1.f / 96.f);
            float var = sq - sm * sm;
            muo[(long long)blockIdx.z * HW + n_base + tid] = sm;
            rso[(long long)blockIdx.z * HW + n_base + tid] = rsqrtf(var + 1e-5f);
        }
    }
}

// ---------------- 3x3 depthwise conv: 32x32 tile, float4 I/O ----------------
__global__ __launch_bounds__(256) void dwconv3(const float* __restrict__ in,
                                               const float* __restrict__ w,
                                               float* __restrict__ out) {
    int zc = blockIdx.z;
    int c = zc % 288;
    const float* src = in  + (long long)zc * HW;
    float*       dst = out + (long long)zc * HW;
    int ox = blockIdx.x * 32, oy = blockIdx.y * 32;
    __shared__ float s[34][40];    // col c <-> gx = ox-4+c ; needed cols 3..36
    int tid = threadIdx.x;
    #pragma unroll
    for (int j = 0; j < 2; j++) {
        int sl = tid + j * 256;
        if (sl < 340) {
            int r = sl / 10, q = sl - r * 10;
            int gy = oy + r - 1, gx = ox - 4 + q * 4;
            float4 v = make_float4(0.f, 0.f, 0.f, 0.f);
            if (gy >= 0 && gy < 256 && gx >= 0 && gx <= 252)
                v = *(const float4*)(src + gy * 256 + gx);
            *(float4*)&s[r][q * 4] = v;
        }
    }
    __syncthreads();
    const float* wc = w + c * 9;
    float w00 = wc[0], w01 = wc[1], w02 = wc[2];
    float w10 = wc[3], w11 = wc[4], w12 = wc[5];
    float w20 = wc[6], w21 = wc[7], w22 = wc[8];
    int row  = tid >> 3;           // 0..31
    int colq = (tid & 7) * 4;      // 0..28
    float v[3][6];
    #pragma unroll
    for (int dr = 0; dr < 3; dr++) {
        float4 m = *(const float4*)&s[row + dr][colq + 4];
        v[dr][0] = s[row + dr][colq + 3];
        v[dr][1] = m.x; v[dr][2] = m.y; v[dr][3] = m.z; v[dr][4] = m.w;
        v[dr][5] = s[row + dr][colq + 8];
    }
    float4 o;
    float* op = (float*)&o;
    #pragma unroll
    for (int t = 0; t < 4; t++) {
        op[t] = w00 * v[0][t] + w01 * v[0][t + 1] + w02 * v[0][t + 2]
              + w10 * v[1][t] + w11 * v[1][t + 1] + w12 * v[1][t + 2]
              + w20 * v[2][t] + w21 * v[2][t + 1] + w22 * v[2][t + 2];
    }
    *(float4*)(dst + (oy + row) * 256 + ox + colq) = o;
}

// ---------------- svp 1x1 conv ----------------
__global__ void svp_kernel(const float* __restrict__ fea, const float* __restrict__ w,
                           float* __restrict__ out) {
    int i = blockIdx.x * blockDim.x + threadIdx.x;
    if (i >= BATCH * HW) return;
    int b = i >> 16, pix = i & 65535;
    const float* f = fea + (long long)b * 3 * HW + pix;
    float f0 = f[0], f1 = f[HW], f2 = f[2 * HW];
    float* o = out + (long long)b * 12 * HW + pix;
    #pragma unroll
    for (int r = 0; r < 12; r++)
        o[(long long)r * HW] = w[r * 3] * f0 + w[r * 3 + 1] * f1 + w[r * 3 + 2] * f2;
}

// ---------------- Gram partials + fused per-row sum of squares ----------------
__global__ __launch_bounds__(672) void gram_kernel(const float* __restrict__ qkvd,
                                                   const float* __restrict__ svpq,
                                                   float* __restrict__ gp,
                                                   float* __restrict__ ss) {
    __shared__ float qs[27 * GPAD];
    __shared__ float ks[24 * GPAD];
    __shared__ float red_s[51];
    int seg = blockIdx.x;
    int bh  = blockIdx.y;
    int b = bh >> 2, h = bh & 3;
    int tid = threadIdx.x;
    int c = tid / 24, d = tid % 24;
    bool active = tid < 648;
    long long segoff = (long long)seg * (HW / NSEG);
    float acc = 0.f;
    float sqacc[3] = {0.f, 0.f, 0.f};
    if (tid < 51) red_s[tid] = 0.f;

    for (int ch = 0; ch < HW / NSEG; ch += GCH) {
        int jj = 0;
        for (int i = tid; i < 51 * (GCH / 4); i += 672, jj++) {
            int row = i / (GCH / 4), col4 = i % (GCH / 4);
            const float* src;
            float* dstb;
            if (row < 27) {
                src = (row < 24) ? qkvd + ((long long)b * 288 + h * 24 + row) * HW
                                 : svpq + ((long long)b * 12 + h * 3 + (row - 24)) * HW;
                dstb = qs + row * GPAD;
            } else {
                int rr = row - 27;
                src = qkvd + ((long long)b * 288 + 96 + h * 24 + rr) * HW;
                dstb = ks + rr * GPAD;
            }
            float4 v = *(const float4*)(src + segoff + ch + col4 * 4);
            *(float4*)(dstb + col4 * 4) = v;
            sqacc[jj] += v.x * v.x + v.y * v.y + v.z * v.z + v.w * v.w;
        }
        __syncthreads();
        if (active) {
            const float4* q4 = (const float4*)(qs + c * GPAD);
            const float4* k4 = (const float4*)(ks + d * GPAD);
            #pragma unroll 8
            for (int p = 0; p < GCH / 4; p++) {
                float4 qv = q4[p], kv = k4[p];
                acc += qv.x * kv.x + qv.y * kv.y + qv.z * kv.z + qv.w * kv.w;
            }
        }
        __syncthreads();
    }
    if (active) gp[((long long)seg * 16 + bh) * 648 + tid] = acc;

    // flush fused sumsq
    {
        int jj = 0;
        for (int i = tid; i < 51 * (GCH / 4); i += 672, jj++) {
            int row = i / (GCH / 4);
            atomicAdd(&red_s[row], sqacc[jj]);
        }
    }
    __syncthreads();
    if (tid < 51) {
        int row = tid;
        int idx;
        if (row < 24)       idx = b * 204 + h * 24 + row;
        else if (row < 27)  idx = b * 204 + 192 + h * 3 + (row - 24);
        else                idx = b * 204 + 96 + h * 24 + (row - 27);
        atomicAdd(&ss[idx], red_s[row]);
    }
}

// ---------------- attn softmax + fold proj_out -> M[b] (bf16 split) ----------------
__global__ void attnm_kernel(const float* __restrict__ gp, const float* __restrict__ ss,
                             const float* __restrict__ temp, const float* __restrict__ projw,
                             __nv_bfloat16* __restrict__ Mh, __nv_bfloat16* __restrict__ Ml) {
    int b = blockIdx.x;
    __shared__ float attn_s[4][27][24];
    int tid = threadIdx.x;
    if (tid < 108) {
        int h = tid / 27, c = tid % 27;
        float ssq = (c < 24) ? ss[b * 204 + h * 24 + c]
                             : ss[b * 204 + 192 + h * 3 + (c - 24)];
        float nq = fmaxf(sqrtf(ssq), 1e-12f);
        float t = temp[h];
        float row[24];
        #pragma unroll
        for (int d = 0; d < 24; d++) {
            float g = 0.f;
            for (int s = 0; s < NSEG; s++)
                g += gp[((long long)s * 16 + b * 4 + h) * 648 + c * 24 + d];
            float nk = fmaxf(sqrtf(ss[b * 204 + 96 + h * 24 + d]), 1e-12f);
            row[d] = g * t / (nq * nk);
        }
        float mx = row[0];
        #pragma unroll
        for (int d = 1; d < 24; d++) mx = fmaxf(mx, row[d]);
        float sum = 0.f;
        #pragma unroll
        for (int d = 0; d < 24; d++) { row[d] = expf(row[d] - mx); sum += row[d]; }
        float inv = 1.f / sum;
        #pragma unroll
        for (int d = 0; d < 24; d++) attn_s[h][c][d] = row[d] * inv;
    }
    __syncthreads();
    for (int e = tid; e < 96 * 96; e += blockDim.x) {
        int o = e / 96, col = e % 96;
        int h = col / 24, d = col % 24;
        float s = 0.f;
        #pragma unroll
        for (int c = 0; c < 27; c++)
            s += projw[o * 108 + h * 27 + c] * attn_s[h][c][d];
        bsplit(s, Mh[b * 9216 + e], Ml[b * 9216 + e]);
    }
}

// ---------------- launch ----------------
extern "C" void kernel_launch(void* const* d_in, const int* in_sizes, int n_in,
                              void* d_out, int out_size) {
    const float* x           = (const float*)d_in[0];
    const float* svp_fea     = (const float*)d_in[1];
    const float* n1w         = (const float*)d_in[2];
    const float* n1b         = (const float*)d_in[3];
    const float* qkv_w       = (const float*)d_in[4];
    const float* qkv_dw_w    = (const float*)d_in[5];
    const float* svp_w       = (const float*)d_in[6];
    const float* temperature = (const float*)d_in[7];
    const float* proj_out_w  = (const float*)d_in[8];
    const float* n2w         = (const float*)d_in[9];
    const float* n2b         = (const float*)d_in[10];
    const float* ffn1_w      = (const float*)d_in[11];
    const float* ffn2_w      = (const float*)d_in[12];
    const float* ffn_out_w   = (const float*)d_in[13];
    float* out = (float*)d_out;

    float *qkv, *qkvd, *svpq, *mu, *rs, *ss, *gp, *bq, *bg;
    __nv_bfloat16 *Mh, *Ml, *Aqh, *Aql, *Agh, *Agl, *Fh, *Fl;
    cudaGetSymbolAddress((void**)&qkv,  g_qkv);
    cudaGetSymbolAddress((void**)&qkvd, g_qkvd);
    cudaGetSymbolAddress((void**)&svpq, g_svpq);
    cudaGetSymbolAddress((void**)&mu,   g_mu);
    cudaGetSymbolAddress((void**)&rs,   g_rs);
    cudaGetSymbolAddress((void**)&ss,   g_ss);
    cudaGetSymbolAddress((void**)&gp,   g_gp);
    cudaGetSymbolAddress((void**)&Mh,   g_Mh);
    cudaGetSymbolAddress((void**)&Ml,   g_Ml);
    cudaGetSymbolAddress((void**)&Aqh,  g_Aqh);
    cudaGetSymbolAddress((void**)&Aql,  g_Aql);
    cudaGetSymbolAddress((void**)&bq,   g_bq);
    cudaGetSymbolAddress((void**)&Agh,  g_Agh);
    cudaGetSymbolAddress((void**)&Agl,  g_Agl);
    cudaGetSymbolAddress((void**)&bg,   g_bg);
    cudaGetSymbolAddress((void**)&Fh,   g_Fh);
    cudaGetSymbolAddress((void**)&Fl,   g_Fl);

    const int GEMM_SMEM = 4 * 2 * 32 * 136 * 2;   // 69632 bytes
    cudaFuncSetAttribute(gemm_t<1, 1, 0, 0>, cudaFuncAttributeMaxDynamicSharedMemorySize, GEMM_SMEM);
    cudaFuncSetAttribute(gemm_t<0, 0, 1, 1>, cudaFuncAttributeMaxDynamicSharedMemorySize, GEMM_SMEM);
    cudaFuncSetAttribute(gemm_t<2, 1, 0, 0>, cudaFuncAttributeMaxDynamicSharedMemorySize, GEMM_SMEM);
    cudaFuncSetAttribute(gemm_t<0, 0, 1, 0>, cudaFuncAttributeMaxDynamicSharedMemorySize, GEMM_SMEM);

    const int pixBlocks = (BATCH * HW + 255) / 256;

    // 0. fold LN weights into split-bf16 A matrices; zero ss
    prep_kernel<<<897, 96>>>(qkv_w, n1w, n1b, ffn1_w, ffn2_w, n2w, n2b, ffn_out_w, ss);
    // 1. LN1 stats
    ln_stats<<<pixBlocks, 256>>>(x, mu, rs);
    // 2. qkv = Aq @ LN(x) + bq
    gemm_t<1, 1, 0, 0><<<dim3(512, 3, BATCH), 256, GEMM_SMEM>>>(Aqh, Aql, x, nullptr, qkv,
        bq, mu, rs, nullptr, nullptr, 288, 96, 96, 0, 96LL * HW, 0, 288LL * HW);
    // 3. depthwise 3x3
    dwconv3<<<dim3(8, 8, BATCH * 288), 256>>>(qkv, qkv_dw_w, qkvd);
    // 4. svp_q
    svp_kernel<<<pixBlocks, 256>>>(svp_fea, svp_w, svpq);
    // 5. Gram partials + fused sumsq
    gram_kernel<<<dim3(NSEG, 16), 672>>>(qkvd, svpq, gp, ss);
    // 6. softmax + fold proj_out -> M[b]
    attnm_kernel<<<BATCH, 128>>>(gp, ss, temperature, proj_out_w, Mh, Ml);
    // 7. x2 = x + M_b @ v -> out, fused LN2 stats
    gemm_t<0, 0, 1, 1><<<dim3(512, 1, BATCH), 256, GEMM_SMEM>>>(Mh, Ml, qkvd + 192LL * HW, x, out,
        nullptr, nullptr, nullptr, mu, rs, 96, 96, 96, 9216, 288LL * HW, 96LL * HW, 96LL * HW);
    // 8. interleaved ffn1/ffn2 GEMM + fused dual-gate -> g (qkv buffer)
    gemm_t<2, 1, 0, 0><<<dim3(512, 4, BATCH), 256, GEMM_SMEM>>>(Agh, Agl, out, nullptr, qkv,
        bg, mu, rs, nullptr, nullptr, 512, 96, 96, 0, 96LL * HW, 0, 288LL * HW);
    // 9. out = out + ffn_out_w @ g
    gemm_t<0, 0, 1, 0><<<dim3(512, 1, BATCH), 256, GEMM_SMEM>>>(Fh, Fl, qkv, out, out,
        nullptr, nullptr, nullptr, nullptr, nullptr, 96, 255, 256, 0, 288LL * HW, 96LL * HW, 96LL * HW);
}